// round 11
// baseline (speedup 1.0000x reference)
#include <cuda_runtime.h>
#include <cuda_bf16.h>
#include <math.h>

#define NN 50000
#define NE 800000
#define D1 128
#define D2 32

// ---------------- scratch (device globals; no allocations) ----------------
__device__ __align__(16) float g_Wh2[(size_t)NN * D2];
__device__ float g_es2[NN], g_ed2[NN];
__device__ int   g_deg[NN];          // histogram, then scatter cursor
__device__ int   g_rowstart[NN + 1];
__device__ int   g_csrc[NE];         // CSR: src node per slot (dst-sorted)
__device__ float g_c1[8], g_c2[8];   // W1 @ a1[:D1], W1 @ a1[D1:]

// ================= CSR build (per launch; topology shared by layers) ======
__global__ void k_zero_deg() {
    int i = blockIdx.x * blockDim.x + threadIdx.x;
    if (i < NN) g_deg[i] = 0;
}

__global__ void k_hist(const int* __restrict__ dst) {
    int e = blockIdx.x * blockDim.x + threadIdx.x;
    if (e < NE) atomicAdd(&g_deg[dst[e]], 1);
}

// single-block exclusive scan of g_deg -> g_rowstart; re-zeroes g_deg (cursor)
__global__ void k_scan() {
    const int T = 1024;
    const int CH = (NN + T - 1) / T;  // 49
    int t = threadIdx.x;
    int base = t * CH;

    int s = 0;
    for (int i = 0; i < CH; i++) {
        int idx = base + i;
        if (idx < NN) s += g_deg[idx];
    }
    __shared__ int warpsum[32];
    int lane = t & 31, w = t >> 5;
    int incl = s;
#pragma unroll
    for (int o = 1; o < 32; o <<= 1) {
        int v = __shfl_up_sync(0xffffffffu, incl, o);
        if (lane >= o) incl += v;
    }
    if (lane == 31) warpsum[w] = incl;
    __syncthreads();
    if (w == 0) {
        int v = warpsum[lane];
#pragma unroll
        for (int o = 1; o < 32; o <<= 1) {
            int u = __shfl_up_sync(0xffffffffu, v, o);
            if (lane >= o) v += u;
        }
        warpsum[lane] = v;
    }
    __syncthreads();
    int excl = incl - s + ((w > 0) ? warpsum[w - 1] : 0);

    int run = excl;
    for (int i = 0; i < CH; i++) {
        int idx = base + i;
        if (idx < NN) {
            g_rowstart[idx] = run;
            run += g_deg[idx];
            g_deg[idx] = 0;  // becomes scatter cursor
        }
    }
    if (t == T - 1) g_rowstart[NN] = run;
}

__global__ void k_scatter(const int* __restrict__ src,
                          const int* __restrict__ dst) {
    int e = blockIdx.x * blockDim.x + threadIdx.x;
    if (e >= NE) return;
    int d = dst[e];
    int pos = g_rowstart[d] + atomicAdd(&g_deg[d], 1);
    g_csrc[pos] = src[e];
}

// ================= c1 = W1 @ a1[:D1], c2 = W1 @ a1[D1:] (8 floats each) ===
__global__ void k_c12(const float* __restrict__ W1,
                      const float* __restrict__ a1) {
    int w = threadIdx.x >> 5, lane = threadIdx.x & 31;  // 16 warps
    int k = w & 7;
    const float* av = a1 + ((w < 8) ? 0 : D1);
    float p = 0.f;
    for (int j = lane; j < D1; j += 32) p += W1[k * D1 + j] * av[j];
#pragma unroll
    for (int o = 16; o; o >>= 1) p += __shfl_xor_sync(0xffffffffu, p, o);
    if (lane == 0) {
        if (w < 8) g_c1[k] = p; else g_c2[k] = p;
    }
}

// edge weight: exp(leaky_relu(logit)). Global max-shift dropped: it enters
// only through the +1e-9 denominator term (rel effect ~1e-10 here).
__device__ __forceinline__ float edge_w(float lg) {
    float v = (lg > 0.f) ? lg : 0.2f * lg;
    return __expf(v);
}

// ===== fused layer1: gather x (8-dim!) + @W1 + elu + node2 matvec =========
// aggx = Σ_e w_e x[src_e];  out1 = elu( (aggx @ W1) / (Σw + 1e-9) )
// Wh2  = out1 @ W2 ;  es2/ed2 from a2.
// w_e = exp(leaky(x[s]·c1 + x[node]·c2))   (c1/c2 fold W1 and a1)
__global__ void k_gagg1_node2(const float* __restrict__ x,
                              const float* __restrict__ W1,
                              const float* __restrict__ W2,
                              const float* __restrict__ a2) {
    __shared__ float sW1[8 * D1];   // 4 KB
    __shared__ float sW2[D1 * D2];  // 16 KB
    __shared__ float sa[2 * D2];
    __shared__ float sh[8][D1];     // per-warp out1 row
    int tid = threadIdx.x;
    for (int i = tid; i < 8 * D1; i += blockDim.x) sW1[i] = W1[i];
    for (int i = tid; i < D1 * D2; i += blockDim.x) sW2[i] = W2[i];
    for (int i = tid; i < 2 * D2; i += blockDim.x) sa[i] = a2[i];
    __syncthreads();

    int warp = tid >> 5, lane = tid & 31;
    int node = blockIdx.x * (blockDim.x >> 5) + warp;
    if (node >= NN) return;

    // c1/c2 into registers (broadcast loads)
    float rc1[8], rc2[8];
#pragma unroll
    for (int k = 0; k < 8; k++) { rc1[k] = g_c1[k]; rc2[k] = g_c2[k]; }

    // edc = x[node] . c2   (broadcast row load, all lanes same address)
    const float4* xn = reinterpret_cast<const float4*>(x + (size_t)node * 8);
    float4 nlo = xn[0], nhi = xn[1];
    float edc = nlo.x * rc2[0] + nlo.y * rc2[1] + nlo.z * rc2[2] + nlo.w * rc2[3]
              + nhi.x * rc2[4] + nhi.y * rc2[5] + nhi.z * rc2[6] + nhi.w * rc2[7];

    int beg = g_rowstart[node], end = g_rowstart[node + 1];

    // lane-per-edge gather of x rows (32B each)
    float a0 = 0.f, a1r = 0.f, a2r = 0.f, a3 = 0.f;
    float a4 = 0.f, a5 = 0.f, a6 = 0.f, a7 = 0.f, psum = 0.f;
    for (int i = beg + lane; i < end; i += 32) {
        int s = g_csrc[i];
        const float4* xs = reinterpret_cast<const float4*>(x + (size_t)s * 8);
        float4 lo = xs[0], hi = xs[1];
        float es = lo.x * rc1[0] + lo.y * rc1[1] + lo.z * rc1[2] + lo.w * rc1[3]
                 + hi.x * rc1[4] + hi.y * rc1[5] + hi.z * rc1[6] + hi.w * rc1[7];
        float w = edge_w(es + edc);
        psum += w;
        a0 += w * lo.x; a1r += w * lo.y; a2r += w * lo.z; a3 += w * lo.w;
        a4 += w * hi.x; a5  += w * hi.y; a6  += w * hi.z; a7 += w * hi.w;
    }
    // warp-reduce 9 values (all lanes end with totals)
#pragma unroll
    for (int o = 16; o; o >>= 1) {
        a0  += __shfl_xor_sync(0xffffffffu, a0,  o);
        a1r += __shfl_xor_sync(0xffffffffu, a1r, o);
        a2r += __shfl_xor_sync(0xffffffffu, a2r, o);
        a3  += __shfl_xor_sync(0xffffffffu, a3,  o);
        a4  += __shfl_xor_sync(0xffffffffu, a4,  o);
        a5  += __shfl_xor_sync(0xffffffffu, a5,  o);
        a6  += __shfl_xor_sync(0xffffffffu, a6,  o);
        a7  += __shfl_xor_sync(0xffffffffu, a7,  o);
        psum += __shfl_xor_sync(0xffffffffu, psum, o);
    }

    float inv = 1.f / (psum + 1e-9f);
    // out1[j] = elu( inv * (aggx @ W1)[:,j] ), j = lane + 32*i
#pragma unroll
    for (int i = 0; i < 4; i++) {
        int j = i * 32 + lane;
        float o = a0 * sW1[0 * D1 + j] + a1r * sW1[1 * D1 + j]
                + a2r * sW1[2 * D1 + j] + a3 * sW1[3 * D1 + j]
                + a4 * sW1[4 * D1 + j] + a5 * sW1[5 * D1 + j]
                + a6 * sW1[6 * D1 + j] + a7 * sW1[7 * D1 + j];
        o *= inv;
        o = (o > 0.f) ? o : expm1f(o);  // elu fused
        sh[warp][j] = o;
    }
    __syncwarp();

    // node2: Wh2 = out1 @ W2, es2/ed2
    int j = lane;
    float acc = 0.f;
#pragma unroll 8
    for (int k = 0; k < D1; k++) acc += sh[warp][k] * sW2[k * D2 + j];

    g_Wh2[(size_t)node * D2 + j] = acc;

    float es = acc * sa[j];
    float ed = acc * sa[D2 + j];
#pragma unroll
    for (int o = 16; o; o >>= 1) {
        es += __shfl_down_sync(0xffffffffu, es, o);
        ed += __shfl_down_sync(0xffffffffu, ed, o);
    }
    if (lane == 0) {
        g_es2[node] = es;
        g_ed2[node] = ed;
    }
}

// ====== fused: chunked gather layer2 (D=32) + elu + MLP head ==============
__global__ void k_gagg2_head(const float* __restrict__ hw1,
                             const float* __restrict__ hb1,
                             const float* __restrict__ hw2,
                             const float* __restrict__ hb2,
                             float* __restrict__ out) {
    __shared__ float sw1[32 * 32];
    __shared__ float sb1[32];
    __shared__ float sw2[32];
    __shared__ float sh[8][32];
    int tid = threadIdx.x;
    for (int i = tid; i < 32 * 32; i += blockDim.x) sw1[i] = hw1[i];
    if (tid < 32) { sb1[tid] = hb1[tid]; sw2[tid] = hw2[tid]; }
    __syncthreads();

    int warp = tid >> 5, lane = tid & 31;
    int node = blockIdx.x * (blockDim.x >> 5) + warp;
    if (node >= NN) return;

    int beg = g_rowstart[node], end = g_rowstart[node + 1];
    float edc = g_ed2[node];

    float acc = 0.f, psum = 0.f;
    for (int base = beg; base < end; base += 32) {
        int cnt = min(32, end - base);
        int   s = 0;
        float w = 0.f;
        if (lane < cnt) {
            s = g_csrc[base + lane];
            w = edge_w(g_es2[s] + edc);
        }
        psum += w;
        if (cnt == 32) {
#pragma unroll 8
            for (int j = 0; j < 32; j++) {
                int   sj = __shfl_sync(0xffffffffu, s, j);
                float wj = __shfl_sync(0xffffffffu, w, j);
                acc += wj * g_Wh2[(size_t)sj * D2 + lane];
            }
        } else {
            for (int j = 0; j < cnt; j++) {
                int   sj = __shfl_sync(0xffffffffu, s, j);
                float wj = __shfl_sync(0xffffffffu, w, j);
                acc += wj * g_Wh2[(size_t)sj * D2 + lane];
            }
        }
    }
    float asum = psum;
#pragma unroll
    for (int o = 16; o; o >>= 1) asum += __shfl_xor_sync(0xffffffffu, asum, o);

    acc *= 1.f / (asum + 1e-9f);
    float h = (acc > 0.f) ? acc : expm1f(acc);   // elu fused

    sh[warp][lane] = h;
    __syncwarp();

    float z = sb1[lane];
#pragma unroll 8
    for (int k = 0; k < 32; k++) z += sh[warp][k] * sw1[k * 32 + lane];

    // exact gelu: 0.5*x*(1+erf(x/sqrt(2)))
    float g = 0.5f * z * (1.f + erff(z * 0.70710678118654752f));
    float sc = g * sw2[lane];
#pragma unroll
    for (int o = 16; o; o >>= 1) sc += __shfl_down_sync(0xffffffffu, sc, o);
    if (lane == 0) out[node] = sc + hb2[0];
}

// ================= launch ==================================================
extern "C" void kernel_launch(void* const* d_in, const int* in_sizes, int n_in,
                              void* d_out, int out_size) {
    const float* x   = (const float*)d_in[0];
    const int* ei    = (const int*)d_in[1];     // int32 (JAX x64 disabled)
    const float* W1  = (const float*)d_in[2];
    const float* a1  = (const float*)d_in[3];
    const float* W2  = (const float*)d_in[4];
    const float* a2  = (const float*)d_in[5];
    const float* hw1 = (const float*)d_in[6];
    const float* hb1 = (const float*)d_in[7];
    const float* hw2 = (const float*)d_in[8];
    const float* hb2 = (const float*)d_in[9];
    float* out       = (float*)d_out;

    const int* src = ei;        // edge_index[0, :]
    const int* dst = ei + NE;   // edge_index[1, :]

    const int TB = 256;
    const int nodeBlocks = (NN + 7) / 8;        // warp per node, 8 warps/block
    const int edgeBlocks = (NE + TB - 1) / TB;
    const int zeroBlocks = (NN + TB - 1) / TB;

    // CSR build
    k_zero_deg<<<zeroBlocks, TB>>>();
    k_hist<<<edgeBlocks, TB>>>(dst);
    k_scan<<<1, 1024>>>();
    k_scatter<<<edgeBlocks, TB>>>(src, dst);

    // folded attention vectors
    k_c12<<<1, 512>>>(W1, a1);

    // layer 1 (x-space gather) + fused layer-2 projection
    k_gagg1_node2<<<nodeBlocks, TB>>>(x, W1, W2, a2);

    // layer 2 gather + fused head
    k_gagg2_head<<<nodeBlocks, TB>>>(hw1, hb1, hw2, hb2, out);
}

// round 12
// speedup vs baseline: 1.5139x; 1.5139x over previous
#include <cuda_runtime.h>
#include <cuda_bf16.h>
#include <math.h>

#define NN 50000
#define NE 800000
#define D1 128
#define D2 32

// ---------------- scratch (device globals; no allocations) ----------------
__device__ __align__(16) float g_Wh2[(size_t)NN * D2];
__device__ __align__(16) float g_xg[(size_t)NE * 8];   // permuted x rows (CSR order)
__device__ float g_es2[NN], g_ed2[NN];
__device__ int   g_deg[NN];          // histogram, then scatter cursor
__device__ int   g_rowstart[NN + 1];
__device__ int   g_csrc[NE];         // CSR: src node per slot (dst-sorted)
__device__ float g_c1[8], g_c2[8];   // W1 @ a1[:D1], W1 @ a1[D1:]

// ================= CSR build (per launch; topology shared by layers) ======
__global__ void k_zero_deg() {
    int i = blockIdx.x * blockDim.x + threadIdx.x;
    if (i < NN) g_deg[i] = 0;
}

__global__ void k_hist(const int* __restrict__ dst) {
    int e = blockIdx.x * blockDim.x + threadIdx.x;
    if (e < NE) atomicAdd(&g_deg[dst[e]], 1);
}

// single-block exclusive scan of g_deg -> g_rowstart; re-zeroes g_deg (cursor)
__global__ void k_scan() {
    const int T = 1024;
    const int CH = (NN + T - 1) / T;  // 49
    int t = threadIdx.x;
    int base = t * CH;

    int s = 0;
    for (int i = 0; i < CH; i++) {
        int idx = base + i;
        if (idx < NN) s += g_deg[idx];
    }
    __shared__ int warpsum[32];
    int lane = t & 31, w = t >> 5;
    int incl = s;
#pragma unroll
    for (int o = 1; o < 32; o <<= 1) {
        int v = __shfl_up_sync(0xffffffffu, incl, o);
        if (lane >= o) incl += v;
    }
    if (lane == 31) warpsum[w] = incl;
    __syncthreads();
    if (w == 0) {
        int v = warpsum[lane];
#pragma unroll
        for (int o = 1; o < 32; o <<= 1) {
            int u = __shfl_up_sync(0xffffffffu, v, o);
            if (lane >= o) v += u;
        }
        warpsum[lane] = v;
    }
    __syncthreads();
    int excl = incl - s + ((w > 0) ? warpsum[w - 1] : 0);

    int run = excl;
    for (int i = 0; i < CH; i++) {
        int idx = base + i;
        if (idx < NN) {
            g_rowstart[idx] = run;
            run += g_deg[idx];
            g_deg[idx] = 0;  // becomes scatter cursor
        }
    }
    if (t == T - 1) g_rowstart[NN] = run;
}

__global__ void k_scatter(const int* __restrict__ src,
                          const int* __restrict__ dst) {
    int e = blockIdx.x * blockDim.x + threadIdx.x;
    if (e >= NE) return;
    int d = dst[e];
    int pos = g_rowstart[d] + atomicAdd(&g_deg[d], 1);
    g_csrc[pos] = src[e];
}

// permute x rows into CSR slot order: coalesced writes, cached scattered reads
__global__ void k_permx(const float* __restrict__ x) {
    int i = blockIdx.x * blockDim.x + threadIdx.x;
    if (i >= NE) return;
    int s = g_csrc[i];
    const float4* xs = reinterpret_cast<const float4*>(x + (size_t)s * 8);
    float4* o = reinterpret_cast<float4*>(g_xg) + (size_t)i * 2;
    float4 lo = xs[0], hi = xs[1];
    o[0] = lo; o[1] = hi;
}

// ================= c1 = W1 @ a1[:D1], c2 = W1 @ a1[D1:] (8 floats each) ===
__global__ void k_c12(const float* __restrict__ W1,
                      const float* __restrict__ a1) {
    int w = threadIdx.x >> 5, lane = threadIdx.x & 31;  // 16 warps
    int k = w & 7;
    const float* av = a1 + ((w < 8) ? 0 : D1);
    float p = 0.f;
    for (int j = lane; j < D1; j += 32) p += W1[k * D1 + j] * av[j];
#pragma unroll
    for (int o = 16; o; o >>= 1) p += __shfl_xor_sync(0xffffffffu, p, o);
    if (lane == 0) {
        if (w < 8) g_c1[k] = p; else g_c2[k] = p;
    }
}

// edge weight: exp(leaky_relu(logit)). Global max-shift dropped: it enters
// only through the +1e-9 denominator term (rel effect ~1e-10 here).
__device__ __forceinline__ float edge_w(float lg) {
    float v = (lg > 0.f) ? lg : 0.2f * lg;
    return __expf(v);
}

// ===== fused layer1: coalesced x-row gather + @W1 + elu + node2 matvec ====
// aggx = Σ_e w_e x[src_e] (rows streamed from g_xg, 2 lanes per edge)
// w_e  = exp(leaky(x[s]·c1 + x[node]·c2));  out1 = elu(aggx@W1 / (Σw+1e-9))
// Wh2  = out1 @ W2 ;  es2/ed2 from a2.
__global__ void k_gagg1_node2(const float* __restrict__ x,
                              const float* __restrict__ W1,
                              const float* __restrict__ W2,
                              const float* __restrict__ a2) {
    __shared__ float sW1[8 * D1];    // 4 KB
    __shared__ float sW2[D1 * D2];   // 16 KB
    __shared__ float sa[2 * D2];
    __shared__ float sh[16][D1];     // per-warp out1 row (16 warps)
    int tid = threadIdx.x;
    for (int i = tid; i < 8 * D1; i += blockDim.x) sW1[i] = W1[i];
    for (int i = tid; i < D1 * D2; i += blockDim.x) sW2[i] = W2[i];
    for (int i = tid; i < 2 * D2; i += blockDim.x) sa[i] = a2[i];
    __syncthreads();

    int warp = tid >> 5, lane = tid & 31;
    int node = blockIdx.x * (blockDim.x >> 5) + warp;
    if (node >= NN) return;

    int half = lane & 1;  // lane pair handles one edge: even=comps 0-3, odd=4-7

    // c1/c2 into registers (broadcast)
    float rc1[8], rc2[8];
#pragma unroll
    for (int k = 0; k < 8; k++) { rc1[k] = g_c1[k]; rc2[k] = g_c2[k]; }
    // this lane's half of c1 for the per-edge dot
    float c40 = half ? rc1[4] : rc1[0];
    float c41 = half ? rc1[5] : rc1[1];
    float c42 = half ? rc1[6] : rc1[2];
    float c43 = half ? rc1[7] : rc1[3];

    // edc = x[node] . c2 (broadcast row load)
    const float4* xn = reinterpret_cast<const float4*>(x + (size_t)node * 8);
    float4 nlo = xn[0], nhi = xn[1];
    float edc = nlo.x * rc2[0] + nlo.y * rc2[1] + nlo.z * rc2[2] + nlo.w * rc2[3]
              + nhi.x * rc2[4] + nhi.y * rc2[5] + nhi.z * rc2[6] + nhi.w * rc2[7];

    int beg = g_rowstart[node], end = g_rowstart[node + 1];

    // stream permuted rows: 16 edges per pass, fully coalesced (512B/pass)
    float a0 = 0.f, a1r = 0.f, a2r = 0.f, a3 = 0.f, psum = 0.f;
    for (int base = beg; base < end; base += 16) {
        int idx = base + (lane >> 1);
        bool valid = idx < end;
        float4 v = make_float4(0.f, 0.f, 0.f, 0.f);
        float p = 0.f;
        if (valid) {
            v = reinterpret_cast<const float4*>(g_xg)[(size_t)idx * 2 + half];
            p = v.x * c40 + v.y * c41 + v.z * c42 + v.w * c43;
        }
        float es = p + __shfl_xor_sync(0xffffffffu, p, 1);  // full 8-dot
        float w = valid ? edge_w(es + edc) : 0.f;
        if (half == 0) psum += w;   // count each edge once
        a0 += w * v.x; a1r += w * v.y; a2r += w * v.z; a3 += w * v.w;
    }
    // reduce over lane pairs (strides 2..16); even lanes: lo sums, odd: hi sums
#pragma unroll
    for (int o = 2; o <= 16; o <<= 1) {
        a0  += __shfl_xor_sync(0xffffffffu, a0,  o);
        a1r += __shfl_xor_sync(0xffffffffu, a1r, o);
        a2r += __shfl_xor_sync(0xffffffffu, a2r, o);
        a3  += __shfl_xor_sync(0xffffffffu, a3,  o);
        psum += __shfl_xor_sync(0xffffffffu, psum, o);
    }
    psum += __shfl_xor_sync(0xffffffffu, psum, 1);  // broadcast to odd lanes

    // exchange halves so every lane holds the full aggx[8]
    float t0 = __shfl_xor_sync(0xffffffffu, a0,  1);
    float t1 = __shfl_xor_sync(0xffffffffu, a1r, 1);
    float t2 = __shfl_xor_sync(0xffffffffu, a2r, 1);
    float t3 = __shfl_xor_sync(0xffffffffu, a3,  1);
    float b0 = half ? t0 : a0,  b4 = half ? a0  : t0;
    float b1 = half ? t1 : a1r, b5 = half ? a1r : t1;
    float b2 = half ? t2 : a2r, b6 = half ? a2r : t2;
    float b3 = half ? t3 : a3,  b7 = half ? a3  : t3;

    float inv = 1.f / (psum + 1e-9f);
    // out1[j] = elu( inv * (aggx @ W1)[j] )
#pragma unroll
    for (int i = 0; i < 4; i++) {
        int j = i * 32 + lane;
        float o = b0 * sW1[0 * D1 + j] + b1 * sW1[1 * D1 + j]
                + b2 * sW1[2 * D1 + j] + b3 * sW1[3 * D1 + j]
                + b4 * sW1[4 * D1 + j] + b5 * sW1[5 * D1 + j]
                + b6 * sW1[6 * D1 + j] + b7 * sW1[7 * D1 + j];
        o *= inv;
        o = (o > 0.f) ? o : expm1f(o);  // elu fused
        sh[warp][j] = o;
    }
    __syncwarp();

    // node2: Wh2 = out1 @ W2, es2/ed2
    int j = lane;
    float acc = 0.f;
#pragma unroll 8
    for (int k = 0; k < D1; k++) acc += sh[warp][k] * sW2[k * D2 + j];

    g_Wh2[(size_t)node * D2 + j] = acc;

    float es = acc * sa[j];
    float ed = acc * sa[D2 + j];
#pragma unroll
    for (int o = 16; o; o >>= 1) {
        es += __shfl_down_sync(0xffffffffu, es, o);
        ed += __shfl_down_sync(0xffffffffu, ed, o);
    }
    if (lane == 0) {
        g_es2[node] = es;
        g_ed2[node] = ed;
    }
}

// ====== fused: chunked gather layer2 (D=32) + elu + MLP head ==============
__global__ void k_gagg2_head(const float* __restrict__ hw1,
                             const float* __restrict__ hb1,
                             const float* __restrict__ hw2,
                             const float* __restrict__ hb2,
                             float* __restrict__ out) {
    __shared__ float sw1[32 * 32];
    __shared__ float sb1[32];
    __shared__ float sw2[32];
    __shared__ float sh[8][32];
    int tid = threadIdx.x;
    for (int i = tid; i < 32 * 32; i += blockDim.x) sw1[i] = hw1[i];
    if (tid < 32) { sb1[tid] = hb1[tid]; sw2[tid] = hw2[tid]; }
    __syncthreads();

    int warp = tid >> 5, lane = tid & 31;
    int node = blockIdx.x * (blockDim.x >> 5) + warp;
    if (node >= NN) return;

    int beg = g_rowstart[node], end = g_rowstart[node + 1];
    float edc = g_ed2[node];

    float acc = 0.f, psum = 0.f;
    for (int base = beg; base < end; base += 32) {
        int cnt = min(32, end - base);
        int   s = 0;
        float w = 0.f;
        if (lane < cnt) {
            s = g_csrc[base + lane];
            w = edge_w(g_es2[s] + edc);
        }
        psum += w;
        if (cnt == 32) {
#pragma unroll 8
            for (int j = 0; j < 32; j++) {
                int   sj = __shfl_sync(0xffffffffu, s, j);
                float wj = __shfl_sync(0xffffffffu, w, j);
                acc += wj * g_Wh2[(size_t)sj * D2 + lane];
            }
        } else {
            for (int j = 0; j < cnt; j++) {
                int   sj = __shfl_sync(0xffffffffu, s, j);
                float wj = __shfl_sync(0xffffffffu, w, j);
                acc += wj * g_Wh2[(size_t)sj * D2 + lane];
            }
        }
    }
    float asum = psum;
#pragma unroll
    for (int o = 16; o; o >>= 1) asum += __shfl_xor_sync(0xffffffffu, asum, o);

    acc *= 1.f / (asum + 1e-9f);
    float h = (acc > 0.f) ? acc : expm1f(acc);   // elu fused

    sh[warp][lane] = h;
    __syncwarp();

    float z = sb1[lane];
#pragma unroll 8
    for (int k = 0; k < 32; k++) z += sh[warp][k] * sw1[k * 32 + lane];

    // exact gelu: 0.5*x*(1+erf(x/sqrt(2)))
    float g = 0.5f * z * (1.f + erff(z * 0.70710678118654752f));
    float sc = g * sw2[lane];
#pragma unroll
    for (int o = 16; o; o >>= 1) sc += __shfl_down_sync(0xffffffffu, sc, o);
    if (lane == 0) out[node] = sc + hb2[0];
}

// ================= launch ==================================================
extern "C" void kernel_launch(void* const* d_in, const int* in_sizes, int n_in,
                              void* d_out, int out_size) {
    const float* x   = (const float*)d_in[0];
    const int* ei    = (const int*)d_in[1];     // int32 (JAX x64 disabled)
    const float* W1  = (const float*)d_in[2];
    const float* a1  = (const float*)d_in[3];
    const float* W2  = (const float*)d_in[4];
    const float* a2  = (const float*)d_in[5];
    const float* hw1 = (const float*)d_in[6];
    const float* hb1 = (const float*)d_in[7];
    const float* hw2 = (const float*)d_in[8];
    const float* hb2 = (const float*)d_in[9];
    float* out       = (float*)d_out;

    const int* src = ei;        // edge_index[0, :]
    const int* dst = ei + NE;   // edge_index[1, :]

    const int TB = 256;
    const int edgeBlocks = (NE + TB - 1) / TB;
    const int zeroBlocks = (NN + TB - 1) / TB;

    // CSR build + x permute
    k_zero_deg<<<zeroBlocks, TB>>>();
    k_hist<<<edgeBlocks, TB>>>(dst);
    k_scan<<<1, 1024>>>();
    k_scatter<<<edgeBlocks, TB>>>(src, dst);
    k_permx<<<edgeBlocks, TB>>>(x);

    // folded attention vectors
    k_c12<<<1, 512>>>(W1, a1);

    // layer 1 (coalesced x-space gather) + fused layer-2 projection
    k_gagg1_node2<<<(NN + 15) / 16, 512>>>(x, W1, W2, a2);

    // layer 2 gather + fused head
    k_gagg2_head<<<(NN + 7) / 8, TB>>>(hw1, hb1, hw2, hb2, out);
}